// round 14
// baseline (speedup 1.0000x reference)
#include <cuda_runtime.h>
#include <cuda_bf16.h>
#include <cuda_fp16.h>
#include <cstdint>

#define N_NODES 50000
#define E_CAP   700000
#define HEADS   4
#define OUT_CH  16
#define OUT_NEU 32
#define IN_CH   128
#define HID     128   // HEADS*OUT_NEU

// ---- output layout (flat concat of reference return tuple, fp32) ----
#define OFF_OUT    0
#define OFF_IXZ    (N_NODES * 64)                  // 3,200,000
#define OFF_SCALAR (OFF_IXZ + N_NODES)             // 3,250,000
#define OFF_MEAN   (OFF_SCALAR + 1)                // 3,250,001 (ODD -> no vector stores!)
#define OFF_STD    (OFF_MEAN + N_NODES * 64)       // 6,450,001 (ODD -> no vector stores!)

// ---- scratch (device globals; no allocation allowed) ----
__device__ __align__(16) __half g_h16[N_NODES * HID];  // node features (fp16)
__device__ __align__(16) float  g_agg[N_NODES * HID];  // UNNORMALIZED segment-sum (fp32)
__device__ __align__(16) float  g_aI[N_NODES * HEADS]; // h . att_i (fp32-EXACT)
__device__ __align__(16) float  g_aJ[N_NODES * HEADS]; // h . att_j (fp32-EXACT)
__device__ __align__(16) float  g_denom[N_NODES * HEADS];
__device__ __align__(16) float  g_v[IN_CH * 8];        // [k][0..3]=W@attI, [4..7]=W@attJ

__device__ __forceinline__ void red_add_v4(float* gptr, float a, float b, float c, float d) {
    asm volatile("red.global.add.v4.f32 [%0], {%1, %2, %3, %4};"
                 :: "l"(gptr), "f"(a), "f"(b), "f"(c), "f"(d) : "memory");
}
__device__ __forceinline__ void red_add_f32(float* gptr, float a) {
    asm volatile("red.global.add.f32 [%0], %1;" :: "l"(gptr), "f"(a) : "memory");
}
__device__ __forceinline__ float lrelu(float a) {
    return a > 0.0f ? a : 0.2f * a;
}
__device__ __forceinline__ uint32_t f2tf32(float f) {
    uint32_t u;
    asm("cvt.rna.tf32.f32 %0, %1;" : "=r"(u) : "f"(f));
    return u;
}
__device__ __forceinline__ void mma_tf32(float* d, const uint32_t* a, uint32_t b0, uint32_t b1) {
    asm volatile(
        "mma.sync.aligned.m16n8k8.row.col.f32.tf32.tf32.f32 "
        "{%0,%1,%2,%3}, {%4,%5,%6,%7}, {%8,%9}, {%0,%1,%2,%3};"
        : "+f"(d[0]), "+f"(d[1]), "+f"(d[2]), "+f"(d[3])
        : "r"(a[0]), "r"(a[1]), "r"(a[2]), "r"(a[3]), "r"(b0), "r"(b1));
}

// ------------------------- K1: zero agg + denom + scalar
__global__ void zero_kernel(float* __restrict__ out) {
    int i = blockIdx.x * blockDim.x + threadIdx.x;
    int stride = gridDim.x * blockDim.x;
    float4 z = make_float4(0.f, 0.f, 0.f, 0.f);
    for (int k = i; k < N_NODES * HID / 4; k += stride)
        ((float4*)g_agg)[k] = z;
    for (int k = i; k < N_NODES; k += stride)
        ((float4*)g_denom)[k] = z;
    if (i == 0) out[OFF_SCALAR] = 0.0f;
}

// ------------------------- K2: v = [W@attI | W@attJ]  (exact fp32, tiny)
__global__ void vmake_kernel(const float* __restrict__ w,
                             const float* __restrict__ att) {
    int k = threadIdx.x;
    if (k >= IN_CH) return;
#pragma unroll
    for (int hd = 0; hd < 4; hd++) {
        float sI = 0.f, sJ = 0.f;
#pragma unroll 8
        for (int j = 0; j < 32; j++) {
            float wv = w[k * HID + hd * 32 + j];
            sI = fmaf(wv, __ldg(&att[hd * 64 + j]),      sI);
            sJ = fmaf(wv, __ldg(&att[hd * 64 + 32 + j]), sJ);
        }
        g_v[k * 8 + hd]     = sI;
        g_v[k * 8 + 4 + hd] = sJ;
    }
}

// ------------------------- K3: exact logits aI/aJ = x @ v  (warp per node)
__global__ __launch_bounds__(256) void alog_kernel(const float* __restrict__ x) {
    __shared__ float sv[IN_CH * 8];
    int tid = threadIdx.x;
    ((float4*)sv)[tid] = ((const float4*)g_v)[tid];   // 256*4 = 1024 floats
    __syncthreads();

    int warp = tid >> 5, lane = tid & 31;
    int n = blockIdx.x * 8 + warp;
    if (n >= N_NODES) return;

    float s[8];
#pragma unroll
    for (int j = 0; j < 8; j++) s[j] = 0.f;
#pragma unroll
    for (int t = 0; t < 4; t++) {
        int k = t * 32 + lane;
        float xv = x[n * IN_CH + k];
#pragma unroll
        for (int j = 0; j < 8; j++) s[j] = fmaf(xv, sv[k * 8 + j], s[j]);
    }
#pragma unroll
    for (int j = 0; j < 8; j++) {
#pragma unroll
        for (int o = 16; o; o >>= 1) s[j] += __shfl_xor_sync(0xffffffffu, s[j], o);
    }
    if (lane == 0) {
#pragma unroll
        for (int hd = 0; hd < 4; hd++) {
            g_aI[n * 4 + hd] = s[hd];
            g_aJ[n * 4 + hd] = s[4 + hd];
        }
    }
}

// ------------------- K4 (profiled): TF32 tensor-core GEMM -> h (fp16)
// BM=64 rows/block, 256 thr = 8 warps: warp w -> rows (w&3)*16..+15,
// col half (w>>2)*64..+63 (8 n-tiles of m16n8). K chunked in 2 x 64.
// A = x as tf32 hi+lo (x exact to 2^-22); B = tf32(W) (only w rounded).
#define BM 64
#define KC 64
#define XPITCH 68     // bank-conflict-free for A frag pattern
#define WPITCH 136    // bank-conflict-free for B frag pattern
#define GEMM_SMEM ((2 * KC * XPITCH + KC * WPITCH) * 4)   // 69,632 B -> 3 blocks/SM

__global__ __launch_bounds__(256, 3) void gemm_kernel(
    const float* __restrict__ x, const float* __restrict__ w)
{
    extern __shared__ uint32_t smu[];
    uint32_t* sXh = smu;                      // [r][kk] pitch 68
    uint32_t* sXl = smu + KC * XPITCH;        // [r][kk] pitch 68
    uint32_t* sWh = smu + 2 * KC * XPITCH;    // [kk][col] pitch 136

    const int tid = threadIdx.x;
    const int warp = tid >> 5, lane = tid & 31;
    const int g = lane >> 2, tg = lane & 3;
    const int rbase = (warp & 3) * 16;
    const int cbase = (warp >> 2) * 64;
    const int row0 = blockIdx.x * BM;

    float acc[8][4];
#pragma unroll
    for (int nt = 0; nt < 8; nt++)
#pragma unroll
        for (int q = 0; q < 4; q++) acc[nt][q] = 0.f;

#pragma unroll
    for (int k0 = 0; k0 < IN_CH; k0 += KC) {
        if (k0 > 0) __syncthreads();

        // fill x chunk: 64 rows x 64 k, split hi/lo
        for (int i = tid; i < BM * KC / 4; i += 256) {     // 1024 float4-groups
            int r = i >> 4, kq = (i & 15) * 4;
            int row = row0 + r;
            float4 xv = (row < N_NODES)
                ? *(const float4*)&x[row * IN_CH + k0 + kq]
                : make_float4(0.f, 0.f, 0.f, 0.f);
            float xs[4] = {xv.x, xv.y, xv.z, xv.w};
#pragma unroll
            for (int q = 0; q < 4; q++) {
                uint32_t hb = f2tf32(xs[q]);
                float lo = xs[q] - __uint_as_float(hb);
                sXh[r * XPITCH + kq + q] = hb;
                sXl[r * XPITCH + kq + q] = f2tf32(lo);
            }
        }
        // fill w chunk: 64 k-rows x 128 cols (hi only)
        for (int i = tid; i < KC * HID / 4; i += 256) {    // 2048 float4-groups
            int kk = i >> 5, cq = (i & 31) * 4;
            float4 wv = *(const float4*)&w[(k0 + kk) * HID + cq];
            sWh[kk * WPITCH + cq + 0] = f2tf32(wv.x);
            sWh[kk * WPITCH + cq + 1] = f2tf32(wv.y);
            sWh[kk * WPITCH + cq + 2] = f2tf32(wv.z);
            sWh[kk * WPITCH + cq + 3] = f2tf32(wv.w);
        }
        __syncthreads();

#pragma unroll
        for (int ks = 0; ks < 8; ks++) {
            const int kk0 = ks * 8;
            uint32_t ah[4], al[4];
            {
                int r0 = (rbase + g) * XPITCH, r1 = (rbase + g + 8) * XPITCH;
                int c0 = kk0 + tg, c1 = kk0 + tg + 4;
                ah[0] = sXh[r0 + c0]; ah[1] = sXh[r1 + c0];
                ah[2] = sXh[r0 + c1]; ah[3] = sXh[r1 + c1];
                al[0] = sXl[r0 + c0]; al[1] = sXl[r1 + c0];
                al[2] = sXl[r0 + c1]; al[3] = sXl[r1 + c1];
            }
#pragma unroll
            for (int nt = 0; nt < 8; nt++) {
                const int col = cbase + nt * 8 + g;
                uint32_t b0 = sWh[(kk0 + tg) * WPITCH + col];
                uint32_t b1 = sWh[(kk0 + tg + 4) * WPITCH + col];
                mma_tf32(acc[nt], ah, b0, b1);
                mma_tf32(acc[nt], al, b0, b1);
            }
        }
    }

    // ---- epilogue: store h as fp16 ----
    const int row_lo = row0 + rbase + g;
    const int row_hi = row_lo + 8;
#pragma unroll
    for (int nt = 0; nt < 8; nt++) {
        const int col = cbase + nt * 8 + 2 * tg;
        if (row_lo < N_NODES)
            *(__half2*)&g_h16[row_lo * HID + col] =
                __floats2half2_rn(acc[nt][0], acc[nt][1]);
        if (row_hi < N_NODES)
            *(__half2*)&g_h16[row_hi * HID + col] =
                __floats2half2_rn(acc[nt][2], acc[nt][3]);
    }
}

// ------- K5: FUSED edge pass over RANDOM edges only (measured 84.7us).
// 16 threads/edge; lanes 0-3 compute the 4 heads' exps, shfl broadcasts.
// agg[dst] += e*h[src] (2x red.v4/lane); denom[dst] += e (lanes 0-3).
// No max subtraction: e/(denom+eps) scale invariant (validated R4-R13).
__global__ void edge_fused(const int* __restrict__ src,
                           const int* __restrict__ dst, int E_rand)
{
    int g = blockIdx.x * blockDim.x + threadIdx.x;
    int e = g >> 4;
    if (e >= E_rand) return;
    int lane = g & 15;
    int s = src[e], d = dst[e];

    float myexp = 0.0f;
    if (lane < 4) {
        float a = __ldg(&g_aI[d * 4 + lane]) + __ldg(&g_aJ[s * 4 + lane]);
        myexp = __expf(lrelu(a));
    }
    const int head = lane >> 2;
    const float ev = __shfl_sync(0xffffffffu, myexp, head, 16);

    const uint4 hv = *(const uint4*)&g_h16[s * HID + lane * 8];
    float2 f0 = __half22float2(*(const half2*)&hv.x);
    float2 f1 = __half22float2(*(const half2*)&hv.y);
    float2 f2 = __half22float2(*(const half2*)&hv.z);
    float2 f3 = __half22float2(*(const half2*)&hv.w);

    float* base = &g_agg[d * HID + lane * 8];
    red_add_v4(base,     f0.x * ev, f0.y * ev, f1.x * ev, f1.y * ev);
    red_add_v4(base + 4, f2.x * ev, f2.y * ev, f3.x * ev, f3.y * ev);
    if (lane < 4)
        red_add_f32(&g_denom[d * 4 + lane], myexp);
}

// ------------------------- K6: VIB epilogue + self-loop + outputs
__global__ __launch_bounds__(256) void finalize_kernel(
    const float* __restrict__ bias, float* __restrict__ out)
{
    int warp = threadIdx.x >> 5, lane = threadIdx.x & 31;
    int n = blockIdx.x * 8 + warp;
    if (n >= N_NODES) return;
    int head = lane >> 3, cc = lane & 7;

    // self-loop contribution (edge list tail: src=dst=n)
    const float es = __expf(lrelu(__ldg(&g_aI[n * 4 + head]) +
                                  __ldg(&g_aJ[n * 4 + head])));
    const float inv = 1.0f / (__ldg(&g_denom[n * 4 + head]) + es + 1e-16f);

    float kl = 0.0f;
#pragma unroll
    for (int t = 0; t < 2; t++) {
        int c = cc + t * 8;
        int chM = head * 32 + c;
        int chS = head * 32 + 16 + c;
        float hm = __half2float(g_h16[n * HID + chM]);
        float hs = __half2float(g_h16[n * HID + chS]);
        float mv = (g_agg[n * HID + chM] + es * hm) * inv + bias[chM];
        float sp = (g_agg[n * HID + chS] + es * hs) * inv + bias[chS] - 5.0f;
        float st = fmaxf(sp, 0.0f) + log1pf(expf(-fabsf(sp))) + 1e-10f;
        kl += -logf(st) + 0.5f * (st * st + mv * mv) - 0.5f;
        out[OFF_OUT  + n * 64 + head * 16 + c] = mv;
        out[OFF_MEAN + n * 64 + head * 16 + c] = mv;
        out[OFF_STD  + n * 64 + head * 16 + c] = st;
    }
#pragma unroll
    for (int o = 16; o; o >>= 1) kl += __shfl_xor_sync(0xffffffffu, kl, o);
    if (lane == 0) out[OFF_IXZ + n] = kl * 0.25f;
}

// ---------------------------------------------------------------- launch
extern "C" void kernel_launch(void* const* d_in, const int* in_sizes, int n_in,
                              void* d_out, int out_size)
{
    const float* x    = (const float*)d_in[0];
    const int*   ei   = (const int*)d_in[1];
    const float* w    = (const float*)d_in[2];
    const float* att  = (const float*)d_in[3];
    const float* bias = (const float*)d_in[4];
    float* out = (float*)d_out;

    const int E = in_sizes[1] / 2;
    const int E_rand = E - N_NODES;    // tail N_NODES entries are self-loops
    const int* src = ei;
    const int* dst = ei + E;

    cudaFuncSetAttribute(gemm_kernel,
                         cudaFuncAttributeMaxDynamicSharedMemorySize, GEMM_SMEM);

    // launch order: gemm is #4 (ncu profiles launch #4)
    zero_kernel<<<512, 256>>>(out);
    vmake_kernel<<<1, 128>>>(w, att);
    alog_kernel<<<(N_NODES + 7) / 8, 256>>>(x);
    gemm_kernel<<<(N_NODES + BM - 1) / BM, 256, GEMM_SMEM>>>(x, w);
    edge_fused<<<(E_rand * 16 + 255) / 256, 256>>>(src, dst, E_rand);
    finalize_kernel<<<(N_NODES + 7) / 8, 256>>>(bias, out);
}

// round 15
// speedup vs baseline: 1.2075x; 1.2075x over previous
#include <cuda_runtime.h>
#include <cuda_bf16.h>
#include <cuda_fp16.h>
#include <cstdint>

#define N_NODES 50000
#define E_CAP   700000
#define HEADS   4
#define OUT_CH  16
#define OUT_NEU 32
#define IN_CH   128
#define HID     128   // HEADS*OUT_NEU

// ---- output layout (flat concat of reference return tuple, fp32) ----
#define OFF_OUT    0
#define OFF_IXZ    (N_NODES * 64)                  // 3,200,000
#define OFF_SCALAR (OFF_IXZ + N_NODES)             // 3,250,000
#define OFF_MEAN   (OFF_SCALAR + 1)                // 3,250,001 (ODD -> no vector stores!)
#define OFF_STD    (OFF_MEAN + N_NODES * 64)       // 6,450,001 (ODD -> no vector stores!)

// ---- scratch (device globals; no allocation allowed) ----
__device__ __align__(16) __half g_h16[N_NODES * HID];  // node features (fp16)
__device__ __align__(16) float  g_agg[N_NODES * HID];  // UNNORMALIZED segment-sum (fp32)
__device__ __align__(16) float  g_aI[N_NODES * HEADS]; // h . att_i
__device__ __align__(16) float  g_aJ[N_NODES * HEADS]; // h . att_j
__device__ __align__(16) float  g_denom[N_NODES * HEADS];

__device__ __forceinline__ void red_add_v4(float* gptr, float a, float b, float c, float d) {
    asm volatile("red.global.add.v4.f32 [%0], {%1, %2, %3, %4};"
                 :: "l"(gptr), "f"(a), "f"(b), "f"(c), "f"(d) : "memory");
}
__device__ __forceinline__ void red_add_f32(float* gptr, float a) {
    asm volatile("red.global.add.f32 [%0], %1;" :: "l"(gptr), "f"(a) : "memory");
}
__device__ __forceinline__ float lrelu(float a) {
    return a > 0.0f ? a : 0.2f * a;
}
__device__ __forceinline__ uint32_t f2tf32(float f) {
    uint32_t u;
    asm("cvt.rna.tf32.f32 %0, %1;" : "=r"(u) : "f"(f));
    return u;
}
__device__ __forceinline__ void mma_tf32(float* d, const uint32_t* a, uint32_t b0, uint32_t b1) {
    asm volatile(
        "mma.sync.aligned.m16n8k8.row.col.f32.tf32.tf32.f32 "
        "{%0,%1,%2,%3}, {%4,%5,%6,%7}, {%8,%9}, {%0,%1,%2,%3};"
        : "+f"(d[0]), "+f"(d[1]), "+f"(d[2]), "+f"(d[3])
        : "r"(a[0]), "r"(a[1]), "r"(a[2]), "r"(a[3]), "r"(b0), "r"(b1));
}

// ------------------------- K1: zero agg + denom
__global__ void zero_kernel() {
    int i = blockIdx.x * blockDim.x + threadIdx.x;
    int stride = gridDim.x * blockDim.x;
    float4 z = make_float4(0.f, 0.f, 0.f, 0.f);
    for (int k = i; k < N_NODES * HID / 4; k += stride)
        ((float4*)g_agg)[k] = z;
    for (int k = i; k < N_NODES; k += stride)
        ((float4*)g_denom)[k] = z;
}
// ------------------------- K2: scalar output
__global__ void scalar_kernel(float* __restrict__ out) {
    out[OFF_SCALAR] = 0.0f;
}

// ------------------- K3: TF32 tensor-core GEMM -> h (fp16) + logits (from acc)
// BM=64 rows/block, 256 thr = 8 warps: warp w -> rows (w&3)*16..+15,
// col half (w>>2)*64..+63 (8 n-tiles of m16n8). K chunked in 2 x 64.
// A = x as tf32 hi+lo (x exact to 2^-22); B = tf32(W) (only w rounded).
// Logits aI/aJ computed in-epilogue from fp32 accumulators: error class
// identical to the tf32-w rounding already present in h.
#define BM 64
#define KC 64
#define XPITCH 68     // bank-conflict-free for A frag pattern
#define WPITCH 136    // bank-conflict-free for B frag pattern
#define GEMM_SMEM ((2 * KC * XPITCH + KC * WPITCH) * 4)   // 69,632 B -> 3 blocks/SM

__global__ __launch_bounds__(256, 3) void gemm_kernel(
    const float* __restrict__ x, const float* __restrict__ w,
    const float* __restrict__ att)
{
    extern __shared__ uint32_t smu[];
    uint32_t* sXh = smu;                      // [r][kk] pitch 68
    uint32_t* sXl = smu + KC * XPITCH;        // [r][kk] pitch 68
    uint32_t* sWh = smu + 2 * KC * XPITCH;    // [kk][col] pitch 136

    const int tid = threadIdx.x;
    const int warp = tid >> 5, lane = tid & 31;
    const int g = lane >> 2, tg = lane & 3;
    const int rbase = (warp & 3) * 16;
    const int cbase = (warp >> 2) * 64;
    const int row0 = blockIdx.x * BM;

    float acc[8][4];
#pragma unroll
    for (int nt = 0; nt < 8; nt++)
#pragma unroll
        for (int q = 0; q < 4; q++) acc[nt][q] = 0.f;

#pragma unroll
    for (int k0 = 0; k0 < IN_CH; k0 += KC) {
        if (k0 > 0) __syncthreads();

        // fill x chunk: 64 rows x 64 k, split hi/lo
        for (int i = tid; i < BM * KC / 4; i += 256) {
            int r = i >> 4, kq = (i & 15) * 4;
            int row = row0 + r;
            float4 xv = (row < N_NODES)
                ? *(const float4*)&x[row * IN_CH + k0 + kq]
                : make_float4(0.f, 0.f, 0.f, 0.f);
            float xs[4] = {xv.x, xv.y, xv.z, xv.w};
#pragma unroll
            for (int q = 0; q < 4; q++) {
                uint32_t hb = f2tf32(xs[q]);
                float lo = xs[q] - __uint_as_float(hb);
                sXh[r * XPITCH + kq + q] = hb;
                sXl[r * XPITCH + kq + q] = f2tf32(lo);
            }
        }
        // fill w chunk: 64 k-rows x 128 cols (hi only)
        for (int i = tid; i < KC * HID / 4; i += 256) {
            int kk = i >> 5, cq = (i & 31) * 4;
            float4 wv = *(const float4*)&w[(k0 + kk) * HID + cq];
            sWh[kk * WPITCH + cq + 0] = f2tf32(wv.x);
            sWh[kk * WPITCH + cq + 1] = f2tf32(wv.y);
            sWh[kk * WPITCH + cq + 2] = f2tf32(wv.z);
            sWh[kk * WPITCH + cq + 3] = f2tf32(wv.w);
        }
        __syncthreads();

#pragma unroll
        for (int ks = 0; ks < 8; ks++) {
            const int kk0 = ks * 8;
            uint32_t ah[4], al[4];
            {
                int r0 = (rbase + g) * XPITCH, r1 = (rbase + g + 8) * XPITCH;
                int c0 = kk0 + tg, c1 = kk0 + tg + 4;
                ah[0] = sXh[r0 + c0]; ah[1] = sXh[r1 + c0];
                ah[2] = sXh[r0 + c1]; ah[3] = sXh[r1 + c1];
                al[0] = sXl[r0 + c0]; al[1] = sXl[r1 + c0];
                al[2] = sXl[r0 + c1]; al[3] = sXl[r1 + c1];
            }
#pragma unroll
            for (int nt = 0; nt < 8; nt++) {
                const int col = cbase + nt * 8 + g;
                uint32_t b0 = sWh[(kk0 + tg) * WPITCH + col];
                uint32_t b1 = sWh[(kk0 + tg + 4) * WPITCH + col];
                mma_tf32(acc[nt], ah, b0, b1);
                mma_tf32(acc[nt], al, b0, b1);
            }
        }
    }

    // ---- epilogue: store h as fp16 ----
    const int row_lo = row0 + rbase + g;
    const int row_hi = row_lo + 8;
#pragma unroll
    for (int nt = 0; nt < 8; nt++) {
        const int col = cbase + nt * 8 + 2 * tg;
        if (row_lo < N_NODES)
            *(__half2*)&g_h16[row_lo * HID + col] =
                __floats2half2_rn(acc[nt][0], acc[nt][1]);
        if (row_hi < N_NODES)
            *(__half2*)&g_h16[row_hi * HID + col] =
                __floats2half2_rn(acc[nt][2], acc[nt][3]);
    }

    // ---- epilogue: attention logits from fp32 accumulators ----
    // This thread's cols: cbase + nt*8 + 2*tg + j (j=0,1). Heads split at nt=4.
    const int headA = cbase >> 5, headB = headA + 1;
    float atI[16], atJ[16];
#pragma unroll
    for (int q = 0; q < 16; q++) {
        int col = cbase + (q >> 1) * 8 + 2 * tg + (q & 1);
        int hd = col >> 5, lc = col & 31;
        atI[q] = __ldg(&att[hd * 64 + lc]);
        atJ[q] = __ldg(&att[hd * 64 + 32 + lc]);
    }
    float sIA0 = 0.f, sJA0 = 0.f, sIB0 = 0.f, sJB0 = 0.f;   // row_lo
    float sIA1 = 0.f, sJA1 = 0.f, sIB1 = 0.f, sJB1 = 0.f;   // row_hi
#pragma unroll
    for (int nt = 0; nt < 8; nt++) {
#pragma unroll
        for (int j = 0; j < 2; j++) {
            const float tI = atI[nt * 2 + j], tJ = atJ[nt * 2 + j];
            const float vLo = acc[nt][j], vHi = acc[nt][2 + j];
            if (nt < 4) {
                sIA0 = fmaf(vLo, tI, sIA0); sJA0 = fmaf(vLo, tJ, sJA0);
                sIA1 = fmaf(vHi, tI, sIA1); sJA1 = fmaf(vHi, tJ, sJA1);
            } else {
                sIB0 = fmaf(vLo, tI, sIB0); sJB0 = fmaf(vLo, tJ, sJB0);
                sIB1 = fmaf(vHi, tI, sIB1); sJB1 = fmaf(vHi, tJ, sJB1);
            }
        }
    }
#pragma unroll
    for (int o = 1; o < 4; o <<= 1) {   // reduce over tg (lane bits 0-1)
        sIA0 += __shfl_xor_sync(0xffffffffu, sIA0, o);
        sJA0 += __shfl_xor_sync(0xffffffffu, sJA0, o);
        sIB0 += __shfl_xor_sync(0xffffffffu, sIB0, o);
        sJB0 += __shfl_xor_sync(0xffffffffu, sJB0, o);
        sIA1 += __shfl_xor_sync(0xffffffffu, sIA1, o);
        sJA1 += __shfl_xor_sync(0xffffffffu, sJA1, o);
        sIB1 += __shfl_xor_sync(0xffffffffu, sIB1, o);
        sJB1 += __shfl_xor_sync(0xffffffffu, sJB1, o);
    }
    if (tg == 0) {
        if (row_lo < N_NODES) {
            g_aI[row_lo * HEADS + headA] = sIA0;
            g_aJ[row_lo * HEADS + headA] = sJA0;
            g_aI[row_lo * HEADS + headB] = sIB0;
            g_aJ[row_lo * HEADS + headB] = sJB0;
        }
        if (row_hi < N_NODES) {
            g_aI[row_hi * HEADS + headA] = sIA1;
            g_aJ[row_hi * HEADS + headA] = sJA1;
            g_aI[row_hi * HEADS + headB] = sIB1;
            g_aJ[row_hi * HEADS + headB] = sJB1;
        }
    }
}

// ------- K4 (profiled): FUSED edge pass over RANDOM edges only.
// 16 threads/edge; lanes 0-3 compute the 4 heads' exps, shfl broadcasts.
// agg[dst] += e*h[src] (2x red.v4/lane); denom[dst] += e (lanes 0-3).
// No max subtraction: e/(denom+eps) scale invariant (validated R4-R14).
__global__ void edge_fused(const int* __restrict__ src,
                           const int* __restrict__ dst, int E_rand)
{
    int g = blockIdx.x * blockDim.x + threadIdx.x;
    int e = g >> 4;
    if (e >= E_rand) return;
    int lane = g & 15;
    int s = src[e], d = dst[e];

    float myexp = 0.0f;
    if (lane < 4) {
        float a = __ldg(&g_aI[d * 4 + lane]) + __ldg(&g_aJ[s * 4 + lane]);
        myexp = __expf(lrelu(a));
    }
    const int head = lane >> 2;
    const float ev = __shfl_sync(0xffffffffu, myexp, head, 16);

    const uint4 hv = *(const uint4*)&g_h16[s * HID + lane * 8];
    float2 f0 = __half22float2(*(const half2*)&hv.x);
    float2 f1 = __half22float2(*(const half2*)&hv.y);
    float2 f2 = __half22float2(*(const half2*)&hv.z);
    float2 f3 = __half22float2(*(const half2*)&hv.w);

    float* base = &g_agg[d * HID + lane * 8];
    red_add_v4(base,     f0.x * ev, f0.y * ev, f1.x * ev, f1.y * ev);
    red_add_v4(base + 4, f2.x * ev, f2.y * ev, f3.x * ev, f3.y * ev);
    if (lane < 4)
        red_add_f32(&g_denom[d * 4 + lane], myexp);
}

// ------------------------- K5: VIB epilogue + self-loop + outputs
__global__ __launch_bounds__(256) void finalize_kernel(
    const float* __restrict__ bias, float* __restrict__ out)
{
    int warp = threadIdx.x >> 5, lane = threadIdx.x & 31;
    int n = blockIdx.x * 8 + warp;
    if (n >= N_NODES) return;
    int head = lane >> 3, cc = lane & 7;

    // self-loop contribution (edge list tail: src=dst=n)
    const float es = __expf(lrelu(__ldg(&g_aI[n * 4 + head]) +
                                  __ldg(&g_aJ[n * 4 + head])));
    const float inv = 1.0f / (__ldg(&g_denom[n * 4 + head]) + es + 1e-16f);

    float kl = 0.0f;
#pragma unroll
    for (int t = 0; t < 2; t++) {
        int c = cc + t * 8;
        int chM = head * 32 + c;
        int chS = head * 32 + 16 + c;
        float hm = __half2float(g_h16[n * HID + chM]);
        float hs = __half2float(g_h16[n * HID + chS]);
        float mv = (g_agg[n * HID + chM] + es * hm) * inv + bias[chM];
        float sp = (g_agg[n * HID + chS] + es * hs) * inv + bias[chS] - 5.0f;
        float st = fmaxf(sp, 0.0f) + log1pf(expf(-fabsf(sp))) + 1e-10f;
        kl += -logf(st) + 0.5f * (st * st + mv * mv) - 0.5f;
        out[OFF_OUT  + n * 64 + head * 16 + c] = mv;
        out[OFF_MEAN + n * 64 + head * 16 + c] = mv;
        out[OFF_STD  + n * 64 + head * 16 + c] = st;
    }
#pragma unroll
    for (int o = 16; o; o >>= 1) kl += __shfl_xor_sync(0xffffffffu, kl, o);
    if (lane == 0) out[OFF_IXZ + n] = kl * 0.25f;
}

// ---------------------------------------------------------------- launch
extern "C" void kernel_launch(void* const* d_in, const int* in_sizes, int n_in,
                              void* d_out, int out_size)
{
    const float* x    = (const float*)d_in[0];
    const int*   ei   = (const int*)d_in[1];
    const float* w    = (const float*)d_in[2];
    const float* att  = (const float*)d_in[3];
    const float* bias = (const float*)d_in[4];
    float* out = (float*)d_out;

    const int E = in_sizes[1] / 2;
    const int E_rand = E - N_NODES;    // tail N_NODES entries are self-loops
    const int* src = ei;
    const int* dst = ei + E;

    cudaFuncSetAttribute(gemm_kernel,
                         cudaFuncAttributeMaxDynamicSharedMemorySize, GEMM_SMEM);

    // launch order: edge_fused is #4 (ncu profiles launch #4)
    zero_kernel<<<512, 256>>>();
    scalar_kernel<<<1, 1>>>(out);
    gemm_kernel<<<(N_NODES + BM - 1) / BM, 256, GEMM_SMEM>>>(x, w, att);
    edge_fused<<<(E_rand * 16 + 255) / 256, 256>>>(src, dst, E_rand);
    finalize_kernel<<<(N_NODES + 7) / 8, 256>>>(bias, out);
}

// round 16
// speedup vs baseline: 1.2933x; 1.0710x over previous
#include <cuda_runtime.h>
#include <cuda_bf16.h>
#include <cuda_fp16.h>
#include <cstdint>

#define N_NODES 50000
#define E_CAP   700000
#define HEADS   4
#define OUT_CH  16
#define OUT_NEU 32
#define IN_CH   128
#define HID     128   // HEADS*OUT_NEU

// ---- output layout (flat concat of reference return tuple, fp32) ----
#define OFF_OUT    0
#define OFF_IXZ    (N_NODES * 64)                  // 3,200,000
#define OFF_SCALAR (OFF_IXZ + N_NODES)             // 3,250,000
#define OFF_MEAN   (OFF_SCALAR + 1)                // 3,250,001 (ODD -> no vector stores!)
#define OFF_STD    (OFF_MEAN + N_NODES * 64)       // 6,450,001 (ODD -> no vector stores!)

// ---- scratch (device globals; no allocation allowed) ----
__device__ __align__(16) __half g_h16[N_NODES * HID];  // node features (fp16)
__device__ __align__(16) float  g_agg[N_NODES * HID];  // UNNORMALIZED segment-sum (fp32)
__device__ __align__(16) float  g_aI[N_NODES * HEADS]; // h . att_i
__device__ __align__(16) float  g_aJ[N_NODES * HEADS]; // h . att_j
__device__ __align__(16) float  g_denom[N_NODES * HEADS];

__device__ __forceinline__ void red_add_v4(float* gptr, float a, float b, float c, float d) {
    asm volatile("red.global.add.v4.f32 [%0], {%1, %2, %3, %4};"
                 :: "l"(gptr), "f"(a), "f"(b), "f"(c), "f"(d) : "memory");
}
__device__ __forceinline__ void red_add_f32(float* gptr, float a) {
    asm volatile("red.global.add.f32 [%0], %1;" :: "l"(gptr), "f"(a) : "memory");
}
__device__ __forceinline__ float lrelu(float a) {
    return a > 0.0f ? a : 0.2f * a;
}
__device__ __forceinline__ uint32_t f2tf32(float f) {
    uint32_t u;
    asm("cvt.rna.tf32.f32 %0, %1;" : "=r"(u) : "f"(f));
    return u;
}
__device__ __forceinline__ void mma_tf32(float* d, const uint32_t* a, uint32_t b0, uint32_t b1) {
    asm volatile(
        "mma.sync.aligned.m16n8k8.row.col.f32.tf32.tf32.f32 "
        "{%0,%1,%2,%3}, {%4,%5,%6,%7}, {%8,%9}, {%0,%1,%2,%3};"
        : "+f"(d[0]), "+f"(d[1]), "+f"(d[2]), "+f"(d[3])
        : "r"(a[0]), "r"(a[1]), "r"(a[2]), "r"(a[3]), "r"(b0), "r"(b1));
}

// ------------------- K1: TF32 tensor-core GEMM -> h (fp16) + logits + zeroing
// BM=64 rows/block, 256 thr = 8 warps: warp w -> rows (w&3)*16..+15,
// col half (w>>2)*64..+63 (8 n-tiles of m16n8). K chunked in 2 x 64.
// A = x as tf32 hi+lo (x exact to 2^-22); B = tf32(W) (only w rounded).
// Logits aI/aJ computed in-epilogue from fp32 accumulators. Each block also
// zeroes its rows of g_agg/g_denom (folds the zero kernel into this launch).
#define BM 64
#define KC 64
#define XPITCH 68     // bank-conflict-free for A frag pattern
#define WPITCH 136    // bank-conflict-free for B frag pattern
#define GEMM_SMEM ((2 * KC * XPITCH + KC * WPITCH) * 4)   // 69,632 B -> 3 blocks/SM

__global__ __launch_bounds__(256, 3) void gemm_kernel(
    const float* __restrict__ x, const float* __restrict__ w,
    const float* __restrict__ att)
{
    extern __shared__ uint32_t smu[];
    uint32_t* sXh = smu;                      // [r][kk] pitch 68
    uint32_t* sXl = smu + KC * XPITCH;        // [r][kk] pitch 68
    uint32_t* sWh = smu + 2 * KC * XPITCH;    // [kk][col] pitch 136

    const int tid = threadIdx.x;
    const int warp = tid >> 5, lane = tid & 31;
    const int g = lane >> 2, tg = lane & 3;
    const int rbase = (warp & 3) * 16;
    const int cbase = (warp >> 2) * 64;
    const int row0 = blockIdx.x * BM;

    // ---- zero this block's slice of g_agg / g_denom (replaces zero kernel) ----
    {
        const float4 z = make_float4(0.f, 0.f, 0.f, 0.f);
        const int base4 = row0 * (HID / 4);          // float4 index of row0
        const int lim4 = N_NODES * (HID / 4);
        for (int i = tid; i < BM * (HID / 4); i += 256) {
            int gi = base4 + i;
            if (gi < lim4) ((float4*)g_agg)[gi] = z;
        }
        if (tid < BM) {
            int node = row0 + tid;
            if (node < N_NODES) ((float4*)g_denom)[node] = z;
        }
    }

    float acc[8][4];
#pragma unroll
    for (int nt = 0; nt < 8; nt++)
#pragma unroll
        for (int q = 0; q < 4; q++) acc[nt][q] = 0.f;

#pragma unroll
    for (int k0 = 0; k0 < IN_CH; k0 += KC) {
        if (k0 > 0) __syncthreads();

        // fill x chunk: 64 rows x 64 k, split hi/lo
        for (int i = tid; i < BM * KC / 4; i += 256) {
            int r = i >> 4, kq = (i & 15) * 4;
            int row = row0 + r;
            float4 xv = (row < N_NODES)
                ? *(const float4*)&x[row * IN_CH + k0 + kq]
                : make_float4(0.f, 0.f, 0.f, 0.f);
            float xs[4] = {xv.x, xv.y, xv.z, xv.w};
#pragma unroll
            for (int q = 0; q < 4; q++) {
                uint32_t hb = f2tf32(xs[q]);
                float lo = xs[q] - __uint_as_float(hb);
                sXh[r * XPITCH + kq + q] = hb;
                sXl[r * XPITCH + kq + q] = f2tf32(lo);
            }
        }
        // fill w chunk: 64 k-rows x 128 cols (hi only)
        for (int i = tid; i < KC * HID / 4; i += 256) {
            int kk = i >> 5, cq = (i & 31) * 4;
            float4 wv = *(const float4*)&w[(k0 + kk) * HID + cq];
            sWh[kk * WPITCH + cq + 0] = f2tf32(wv.x);
            sWh[kk * WPITCH + cq + 1] = f2tf32(wv.y);
            sWh[kk * WPITCH + cq + 2] = f2tf32(wv.z);
            sWh[kk * WPITCH + cq + 3] = f2tf32(wv.w);
        }
        __syncthreads();

#pragma unroll
        for (int ks = 0; ks < 8; ks++) {
            const int kk0 = ks * 8;
            uint32_t ah[4], al[4];
            {
                int r0 = (rbase + g) * XPITCH, r1 = (rbase + g + 8) * XPITCH;
                int c0 = kk0 + tg, c1 = kk0 + tg + 4;
                ah[0] = sXh[r0 + c0]; ah[1] = sXh[r1 + c0];
                ah[2] = sXh[r0 + c1]; ah[3] = sXh[r1 + c1];
                al[0] = sXl[r0 + c0]; al[1] = sXl[r1 + c0];
                al[2] = sXl[r0 + c1]; al[3] = sXl[r1 + c1];
            }
#pragma unroll
            for (int nt = 0; nt < 8; nt++) {
                const int col = cbase + nt * 8 + g;
                uint32_t b0 = sWh[(kk0 + tg) * WPITCH + col];
                uint32_t b1 = sWh[(kk0 + tg + 4) * WPITCH + col];
                mma_tf32(acc[nt], ah, b0, b1);
                mma_tf32(acc[nt], al, b0, b1);
            }
        }
    }

    // ---- epilogue: store h as fp16 ----
    const int row_lo = row0 + rbase + g;
    const int row_hi = row_lo + 8;
#pragma unroll
    for (int nt = 0; nt < 8; nt++) {
        const int col = cbase + nt * 8 + 2 * tg;
        if (row_lo < N_NODES)
            *(__half2*)&g_h16[row_lo * HID + col] =
                __floats2half2_rn(acc[nt][0], acc[nt][1]);
        if (row_hi < N_NODES)
            *(__half2*)&g_h16[row_hi * HID + col] =
                __floats2half2_rn(acc[nt][2], acc[nt][3]);
    }

    // ---- epilogue: attention logits from fp32 accumulators ----
    const int headA = cbase >> 5, headB = headA + 1;
    float atI[16], atJ[16];
#pragma unroll
    for (int q = 0; q < 16; q++) {
        int col = cbase + (q >> 1) * 8 + 2 * tg + (q & 1);
        int hd = col >> 5, lc = col & 31;
        atI[q] = __ldg(&att[hd * 64 + lc]);
        atJ[q] = __ldg(&att[hd * 64 + 32 + lc]);
    }
    float sIA0 = 0.f, sJA0 = 0.f, sIB0 = 0.f, sJB0 = 0.f;   // row_lo
    float sIA1 = 0.f, sJA1 = 0.f, sIB1 = 0.f, sJB1 = 0.f;   // row_hi
#pragma unroll
    for (int nt = 0; nt < 8; nt++) {
#pragma unroll
        for (int j = 0; j < 2; j++) {
            const float tI = atI[nt * 2 + j], tJ = atJ[nt * 2 + j];
            const float vLo = acc[nt][j], vHi = acc[nt][2 + j];
            if (nt < 4) {
                sIA0 = fmaf(vLo, tI, sIA0); sJA0 = fmaf(vLo, tJ, sJA0);
                sIA1 = fmaf(vHi, tI, sIA1); sJA1 = fmaf(vHi, tJ, sJA1);
            } else {
                sIB0 = fmaf(vLo, tI, sIB0); sJB0 = fmaf(vLo, tJ, sJB0);
                sIB1 = fmaf(vHi, tI, sIB1); sJB1 = fmaf(vHi, tJ, sJB1);
            }
        }
    }
#pragma unroll
    for (int o = 1; o < 4; o <<= 1) {   // reduce over tg (lane bits 0-1)
        sIA0 += __shfl_xor_sync(0xffffffffu, sIA0, o);
        sJA0 += __shfl_xor_sync(0xffffffffu, sJA0, o);
        sIB0 += __shfl_xor_sync(0xffffffffu, sIB0, o);
        sJB0 += __shfl_xor_sync(0xffffffffu, sJB0, o);
        sIA1 += __shfl_xor_sync(0xffffffffu, sIA1, o);
        sJA1 += __shfl_xor_sync(0xffffffffu, sJA1, o);
        sIB1 += __shfl_xor_sync(0xffffffffu, sIB1, o);
        sJB1 += __shfl_xor_sync(0xffffffffu, sJB1, o);
    }
    if (tg == 0) {
        if (row_lo < N_NODES) {
            g_aI[row_lo * HEADS + headA] = sIA0;
            g_aJ[row_lo * HEADS + headA] = sJA0;
            g_aI[row_lo * HEADS + headB] = sIB0;
            g_aJ[row_lo * HEADS + headB] = sJB0;
        }
        if (row_hi < N_NODES) {
            g_aI[row_hi * HEADS + headA] = sIA1;
            g_aJ[row_hi * HEADS + headA] = sJA1;
            g_aI[row_hi * HEADS + headB] = sIB1;
            g_aJ[row_hi * HEADS + headB] = sJB1;
        }
    }
}

// ------- K2: FUSED edge pass over RANDOM edges only (REDG-floor bound, 88us).
// 16 threads/edge; lanes 0-3 compute the 4 heads' exps, shfl broadcasts.
// agg[dst] += e*h[src] (2x red.v4/lane); denom[dst] += e (lanes 0-3).
// No max subtraction: e/(denom+eps) scale invariant (validated R4-R15).
__global__ void edge_fused(const int* __restrict__ src,
                           const int* __restrict__ dst, int E_rand)
{
    int g = blockIdx.x * blockDim.x + threadIdx.x;
    int e = g >> 4;
    if (e >= E_rand) return;
    int lane = g & 15;
    int s = src[e], d = dst[e];

    float myexp = 0.0f;
    if (lane < 4) {
        float a = __ldg(&g_aI[d * 4 + lane]) + __ldg(&g_aJ[s * 4 + lane]);
        myexp = __expf(lrelu(a));
    }
    const int head = lane >> 2;
    const float ev = __shfl_sync(0xffffffffu, myexp, head, 16);

    const uint4 hv = *(const uint4*)&g_h16[s * HID + lane * 8];
    float2 f0 = __half22float2(*(const half2*)&hv.x);
    float2 f1 = __half22float2(*(const half2*)&hv.y);
    float2 f2 = __half22float2(*(const half2*)&hv.z);
    float2 f3 = __half22float2(*(const half2*)&hv.w);

    float* base = &g_agg[d * HID + lane * 8];
    red_add_v4(base,     f0.x * ev, f0.y * ev, f1.x * ev, f1.y * ev);
    red_add_v4(base + 4, f2.x * ev, f2.y * ev, f3.x * ev, f3.y * ev);
    if (lane < 4)
        red_add_f32(&g_denom[d * 4 + lane], myexp);
}

// ------------------------- K3: VIB epilogue + self-loop + all outputs
__global__ __launch_bounds__(256) void finalize_kernel(
    const float* __restrict__ bias, float* __restrict__ out)
{
    int warp = threadIdx.x >> 5, lane = threadIdx.x & 31;
    int n = blockIdx.x * 8 + warp;
    if (n >= N_NODES) return;
    int head = lane >> 3, cc = lane & 7;

    // self-loop contribution (edge list tail: src=dst=n)
    const float es = __expf(lrelu(__ldg(&g_aI[n * 4 + head]) +
                                  __ldg(&g_aJ[n * 4 + head])));
    const float inv = 1.0f / (__ldg(&g_denom[n * 4 + head]) + es + 1e-16f);

    float kl = 0.0f;
#pragma unroll
    for (int t = 0; t < 2; t++) {
        int c = cc + t * 8;
        int chM = head * 32 + c;
        int chS = head * 32 + 16 + c;
        float hm = __half2float(g_h16[n * HID + chM]);
        float hs = __half2float(g_h16[n * HID + chS]);
        float mv = (g_agg[n * HID + chM] + es * hm) * inv + bias[chM];
        float sp = (g_agg[n * HID + chS] + es * hs) * inv + bias[chS] - 5.0f;
        float st = fmaxf(sp, 0.0f) + log1pf(expf(-fabsf(sp))) + 1e-10f;
        kl += -logf(st) + 0.5f * (st * st + mv * mv) - 0.5f;
        out[OFF_OUT  + n * 64 + head * 16 + c] = mv;
        out[OFF_MEAN + n * 64 + head * 16 + c] = mv;
        out[OFF_STD  + n * 64 + head * 16 + c] = st;
    }
#pragma unroll
    for (int o = 16; o; o >>= 1) kl += __shfl_xor_sync(0xffffffffu, kl, o);
    if (lane == 0) out[OFF_IXZ + n] = kl * 0.25f;
    if (blockIdx.x == 0 && threadIdx.x == 0) out[OFF_SCALAR] = 0.0f;
}

// ---------------------------------------------------------------- launch
extern "C" void kernel_launch(void* const* d_in, const int* in_sizes, int n_in,
                              void* d_out, int out_size)
{
    const float* x    = (const float*)d_in[0];
    const int*   ei   = (const int*)d_in[1];
    const float* w    = (const float*)d_in[2];
    const float* att  = (const float*)d_in[3];
    const float* bias = (const float*)d_in[4];
    float* out = (float*)d_out;

    const int E = in_sizes[1] / 2;
    const int E_rand = E - N_NODES;    // tail N_NODES entries are self-loops
    const int* src = ei;
    const int* dst = ei + E;

    cudaFuncSetAttribute(gemm_kernel,
                         cudaFuncAttributeMaxDynamicSharedMemorySize, GEMM_SMEM);

    // 3 launches total: gemm (zeroes agg/denom) -> edge -> finalize
    gemm_kernel<<<(N_NODES + BM - 1) / BM, 256, GEMM_SMEM>>>(x, w, att);
    edge_fused<<<(E_rand * 16 + 255) / 256, 256>>>(src, dst, E_rand);
    finalize_kernel<<<(N_NODES + 7) / 8, 256>>>(bias, out);
}

// round 17
// speedup vs baseline: 1.3000x; 1.0052x over previous
#include <cuda_runtime.h>
#include <cuda_bf16.h>
#include <cuda_fp16.h>
#include <cstdint>

#define N_NODES 50000
#define E_CAP   700000
#define HEADS   4
#define OUT_CH  16
#define OUT_NEU 32
#define IN_CH   128
#define HID     128   // HEADS*OUT_NEU

// ---- output layout (flat concat of reference return tuple, fp32) ----
#define OFF_OUT    0
#define OFF_IXZ    (N_NODES * 64)                  // 3,200,000
#define OFF_SCALAR (OFF_IXZ + N_NODES)             // 3,250,000
#define OFF_MEAN   (OFF_SCALAR + 1)                // 3,250,001 (ODD -> no vector stores!)
#define OFF_STD    (OFF_MEAN + N_NODES * 64)       // 6,450,001 (ODD -> no vector stores!)

// ---- scratch (device globals; no allocation allowed) ----
__device__ __align__(16) __half g_h16[N_NODES * HID];  // node features (fp16)
__device__ __align__(16) float  g_agg[N_NODES * HID];  // UNNORMALIZED segment-sum (fp32)
__device__ __align__(16) float  g_aI[N_NODES * HEADS]; // h . att_i
__device__ __align__(16) float  g_aJ[N_NODES * HEADS]; // h . att_j
__device__ __align__(16) float  g_denom[N_NODES * HEADS];

__device__ __forceinline__ void red_add_v4(float* gptr, float a, float b, float c, float d) {
    asm volatile("red.global.add.v4.f32 [%0], {%1, %2, %3, %4};"
                 :: "l"(gptr), "f"(a), "f"(b), "f"(c), "f"(d) : "memory");
}
__device__ __forceinline__ void red_add_f32(float* gptr, float a) {
    asm volatile("red.global.add.f32 [%0], %1;" :: "l"(gptr), "f"(a) : "memory");
}
__device__ __forceinline__ float lrelu(float a) {
    return a > 0.0f ? a : 0.2f * a;
}
__device__ __forceinline__ uint32_t f2tf32(float f) {
    uint32_t u;
    asm("cvt.rna.tf32.f32 %0, %1;" : "=r"(u) : "f"(f));
    return u;
}
__device__ __forceinline__ void mma_tf32(float* d, const uint32_t* a, uint32_t b0, uint32_t b1) {
    asm volatile(
        "mma.sync.aligned.m16n8k8.row.col.f32.tf32.tf32.f32 "
        "{%0,%1,%2,%3}, {%4,%5,%6,%7}, {%8,%9}, {%0,%1,%2,%3};"
        : "+f"(d[0]), "+f"(d[1]), "+f"(d[2]), "+f"(d[3])
        : "r"(a[0]), "r"(a[1]), "r"(a[2]), "r"(a[3]), "r"(b0), "r"(b1));
}

// ------------------- K1: TF32 tensor-core GEMM -> h (fp16) + logits + zeroing
// BM=64 rows/block, 256 thr = 8 warps: warp w -> rows (w&3)*16..+15,
// col half (w>>2)*64..+63 (8 n-tiles of m16n8). K chunked in 2 x 64.
// A = x as EXACT hi(tf32-truncate via AND-mask)+lo split; B = tf32(W).
// Logits aI/aJ from fp32 accumulators. Block zeroes its agg/denom rows.
#define BM 64
#define KC 64
#define XPITCH 68     // bank-conflict-free for A frag pattern (68 = 4*17)
#define WPITCH 136    // bank-conflict-free for B frag pattern (136 = 4*34)
#define GEMM_SMEM ((2 * KC * XPITCH + KC * WPITCH) * 4)   // 69,632 B -> 3 blocks/SM

__global__ __launch_bounds__(256, 3) void gemm_kernel(
    const float* __restrict__ x, const float* __restrict__ w,
    const float* __restrict__ att)
{
    extern __shared__ uint32_t smu[];
    uint32_t* sXh = smu;                      // [r][kk] pitch 68
    uint32_t* sXl = smu + KC * XPITCH;        // [r][kk] pitch 68
    uint32_t* sWh = smu + 2 * KC * XPITCH;    // [kk][col] pitch 136

    const int tid = threadIdx.x;
    const int warp = tid >> 5, lane = tid & 31;
    const int g = lane >> 2, tg = lane & 3;
    const int rbase = (warp & 3) * 16;
    const int cbase = (warp >> 2) * 64;
    const int row0 = blockIdx.x * BM;

    // ---- zero this block's slice of g_agg / g_denom ----
    {
        const float4 z = make_float4(0.f, 0.f, 0.f, 0.f);
        const int base4 = row0 * (HID / 4);
        const int lim4 = N_NODES * (HID / 4);
        for (int i = tid; i < BM * (HID / 4); i += 256) {
            int gi = base4 + i;
            if (gi < lim4) ((float4*)g_agg)[gi] = z;
        }
        if (tid < BM) {
            int node = row0 + tid;
            if (node < N_NODES) ((float4*)g_denom)[node] = z;
        }
    }

    float acc[8][4];
#pragma unroll
    for (int nt = 0; nt < 8; nt++)
#pragma unroll
        for (int q = 0; q < 4; q++) acc[nt][q] = 0.f;

#pragma unroll
    for (int k0 = 0; k0 < IN_CH; k0 += KC) {
        if (k0 > 0) __syncthreads();

        // fill x chunk: hi = AND-mask truncation (exact), lo = cvt(x - hi).
        // Vectorized: one STS.128 for 4 hi + one for 4 lo.
        for (int i = tid; i < BM * KC / 4; i += 256) {
            int r = i >> 4, kq = (i & 15) * 4;
            int row = row0 + r;
            float4 xv = (row < N_NODES)
                ? *(const float4*)&x[row * IN_CH + k0 + kq]
                : make_float4(0.f, 0.f, 0.f, 0.f);
            float xs[4] = {xv.x, xv.y, xv.z, xv.w};
            uint4 hi4, lo4;
            uint32_t* hp = (uint32_t*)&hi4;
            uint32_t* lp = (uint32_t*)&lo4;
#pragma unroll
            for (int q = 0; q < 4; q++) {
                uint32_t hb = __float_as_uint(xs[q]) & 0xFFFFE000u;
                hp[q] = hb;
                lp[q] = f2tf32(xs[q] - __uint_as_float(hb));
            }
            *(uint4*)&sXh[r * XPITCH + kq] = hi4;
            *(uint4*)&sXl[r * XPITCH + kq] = lo4;
        }
        // fill w chunk (hi only), vectorized STS.128
        for (int i = tid; i < KC * HID / 4; i += 256) {
            int kk = i >> 5, cq = (i & 31) * 4;
            float4 wv = *(const float4*)&w[(k0 + kk) * HID + cq];
            uint4 t;
            t.x = f2tf32(wv.x); t.y = f2tf32(wv.y);
            t.z = f2tf32(wv.z); t.w = f2tf32(wv.w);
            *(uint4*)&sWh[kk * WPITCH + cq] = t;
        }
        __syncthreads();

#pragma unroll
        for (int ks = 0; ks < 8; ks++) {
            const int kk0 = ks * 8;
            uint32_t ah[4], al[4];
            {
                int r0 = (rbase + g) * XPITCH, r1 = (rbase + g + 8) * XPITCH;
                int c0 = kk0 + tg, c1 = kk0 + tg + 4;
                ah[0] = sXh[r0 + c0]; ah[1] = sXh[r1 + c0];
                ah[2] = sXh[r0 + c1]; ah[3] = sXh[r1 + c1];
                al[0] = sXl[r0 + c0]; al[1] = sXl[r1 + c0];
                al[2] = sXl[r0 + c1]; al[3] = sXl[r1 + c1];
            }
#pragma unroll
            for (int nt = 0; nt < 8; nt++) {
                const int col = cbase + nt * 8 + g;
                uint32_t b0 = sWh[(kk0 + tg) * WPITCH + col];
                uint32_t b1 = sWh[(kk0 + tg + 4) * WPITCH + col];
                mma_tf32(acc[nt], ah, b0, b1);
                mma_tf32(acc[nt], al, b0, b1);
            }
        }
    }

    // ---- epilogue: store h as fp16 ----
    const int row_lo = row0 + rbase + g;
    const int row_hi = row_lo + 8;
#pragma unroll
    for (int nt = 0; nt < 8; nt++) {
        const int col = cbase + nt * 8 + 2 * tg;
        if (row_lo < N_NODES)
            *(__half2*)&g_h16[row_lo * HID + col] =
                __floats2half2_rn(acc[nt][0], acc[nt][1]);
        if (row_hi < N_NODES)
            *(__half2*)&g_h16[row_hi * HID + col] =
                __floats2half2_rn(acc[nt][2], acc[nt][3]);
    }

    // ---- epilogue: attention logits from fp32 accumulators ----
    const int headA = cbase >> 5, headB = headA + 1;
    float atI[16], atJ[16];
#pragma unroll
    for (int q = 0; q < 16; q++) {
        int col = cbase + (q >> 1) * 8 + 2 * tg + (q & 1);
        int hd = col >> 5, lc = col & 31;
        atI[q] = __ldg(&att[hd * 64 + lc]);
        atJ[q] = __ldg(&att[hd * 64 + 32 + lc]);
    }
    float sIA0 = 0.f, sJA0 = 0.f, sIB0 = 0.f, sJB0 = 0.f;   // row_lo
    float sIA1 = 0.f, sJA1 = 0.f, sIB1 = 0.f, sJB1 = 0.f;   // row_hi
#pragma unroll
    for (int nt = 0; nt < 8; nt++) {
#pragma unroll
        for (int j = 0; j < 2; j++) {
            const float tI = atI[nt * 2 + j], tJ = atJ[nt * 2 + j];
            const float vLo = acc[nt][j], vHi = acc[nt][2 + j];
            if (nt < 4) {
                sIA0 = fmaf(vLo, tI, sIA0); sJA0 = fmaf(vLo, tJ, sJA0);
                sIA1 = fmaf(vHi, tI, sIA1); sJA1 = fmaf(vHi, tJ, sJA1);
            } else {
                sIB0 = fmaf(vLo, tI, sIB0); sJB0 = fmaf(vLo, tJ, sJB0);
                sIB1 = fmaf(vHi, tI, sIB1); sJB1 = fmaf(vHi, tJ, sJB1);
            }
        }
    }
#pragma unroll
    for (int o = 1; o < 4; o <<= 1) {   // reduce over tg (lane bits 0-1)
        sIA0 += __shfl_xor_sync(0xffffffffu, sIA0, o);
        sJA0 += __shfl_xor_sync(0xffffffffu, sJA0, o);
        sIB0 += __shfl_xor_sync(0xffffffffu, sIB0, o);
        sJB0 += __shfl_xor_sync(0xffffffffu, sJB0, o);
        sIA1 += __shfl_xor_sync(0xffffffffu, sIA1, o);
        sJA1 += __shfl_xor_sync(0xffffffffu, sJA1, o);
        sIB1 += __shfl_xor_sync(0xffffffffu, sIB1, o);
        sJB1 += __shfl_xor_sync(0xffffffffu, sJB1, o);
    }
    if (tg == 0) {
        if (row_lo < N_NODES) {
            g_aI[row_lo * HEADS + headA] = sIA0;
            g_aJ[row_lo * HEADS + headA] = sJA0;
            g_aI[row_lo * HEADS + headB] = sIB0;
            g_aJ[row_lo * HEADS + headB] = sJB0;
        }
        if (row_hi < N_NODES) {
            g_aI[row_hi * HEADS + headA] = sIA1;
            g_aJ[row_hi * HEADS + headA] = sJA1;
            g_aI[row_hi * HEADS + headB] = sIB1;
            g_aJ[row_hi * HEADS + headB] = sJB1;
        }
    }
}

// ------- K2: FUSED edge pass over RANDOM edges only (LTS red-lane-op floor).
// 16 threads/edge; lanes 0-3 compute the 4 heads' exps, shfl broadcasts.
// agg[dst] += e*h[src] (2x red.v4/lane); denom[dst] += e (lanes 0-3).
// No max subtraction: e/(denom+eps) scale invariant (validated R4-R16).
__global__ void edge_fused(const int* __restrict__ src,
                           const int* __restrict__ dst, int E_rand)
{
    int g = blockIdx.x * blockDim.x + threadIdx.x;
    int e = g >> 4;
    if (e >= E_rand) return;
    int lane = g & 15;
    int s = src[e], d = dst[e];

    float myexp = 0.0f;
    if (lane < 4) {
        float a = __ldg(&g_aI[d * 4 + lane]) + __ldg(&g_aJ[s * 4 + lane]);
        myexp = __expf(lrelu(a));
    }
    const int head = lane >> 2;
    const float ev = __shfl_sync(0xffffffffu, myexp, head, 16);

    const uint4 hv = *(const uint4*)&g_h16[s * HID + lane * 8];
    float2 f0 = __half22float2(*(const half2*)&hv.x);
    float2 f1 = __half22float2(*(const half2*)&hv.y);
    float2 f2 = __half22float2(*(const half2*)&hv.z);
    float2 f3 = __half22float2(*(const half2*)&hv.w);

    float* base = &g_agg[d * HID + lane * 8];
    red_add_v4(base,     f0.x * ev, f0.y * ev, f1.x * ev, f1.y * ev);
    red_add_v4(base + 4, f2.x * ev, f2.y * ev, f3.x * ev, f3.y * ev);
    if (lane < 4)
        red_add_f32(&g_denom[d * 4 + lane], myexp);
}

// ------------------------- K3: VIB epilogue + self-loop + all outputs
__global__ __launch_bounds__(256) void finalize_kernel(
    const float* __restrict__ bias, float* __restrict__ out)
{
    int warp = threadIdx.x >> 5, lane = threadIdx.x & 31;
    int n = blockIdx.x * 8 + warp;
    if (n >= N_NODES) return;
    int head = lane >> 3, cc = lane & 7;

    // self-loop contribution (edge list tail: src=dst=n)
    const float es = __expf(lrelu(__ldg(&g_aI[n * 4 + head]) +
                                  __ldg(&g_aJ[n * 4 + head])));
    const float inv = 1.0f / (__ldg(&g_denom[n * 4 + head]) + es + 1e-16f);

    float kl = 0.0f;
#pragma unroll
    for (int t = 0; t < 2; t++) {
        int c = cc + t * 8;
        int chM = head * 32 + c;
        int chS = head * 32 + 16 + c;
        float hm = __half2float(g_h16[n * HID + chM]);
        float hs = __half2float(g_h16[n * HID + chS]);
        float mv = (g_agg[n * HID + chM] + es * hm) * inv + bias[chM];
        float sp = (g_agg[n * HID + chS] + es * hs) * inv + bias[chS] - 5.0f;
        float st = fmaxf(sp, 0.0f) + log1pf(expf(-fabsf(sp))) + 1e-10f;
        kl += -logf(st) + 0.5f * (st * st + mv * mv) - 0.5f;
        out[OFF_OUT  + n * 64 + head * 16 + c] = mv;
        out[OFF_MEAN + n * 64 + head * 16 + c] = mv;
        out[OFF_STD  + n * 64 + head * 16 + c] = st;
    }
#pragma unroll
    for (int o = 16; o; o >>= 1) kl += __shfl_xor_sync(0xffffffffu, kl, o);
    if (lane == 0) out[OFF_IXZ + n] = kl * 0.25f;
    if (blockIdx.x == 0 && threadIdx.x == 0) out[OFF_SCALAR] = 0.0f;
}

// ---------------------------------------------------------------- launch
extern "C" void kernel_launch(void* const* d_in, const int* in_sizes, int n_in,
                              void* d_out, int out_size)
{
    const float* x    = (const float*)d_in[0];
    const int*   ei   = (const int*)d_in[1];
    const float* w    = (const float*)d_in[2];
    const float* att  = (const float*)d_in[3];
    const float* bias = (const float*)d_in[4];
    float* out = (float*)d_out;

    const int E = in_sizes[1] / 2;
    const int E_rand = E - N_NODES;    // tail N_NODES entries are self-loops
    const int* src = ei;
    const int* dst = ei + E;

    cudaFuncSetAttribute(gemm_kernel,
                         cudaFuncAttributeMaxDynamicSharedMemorySize, GEMM_SMEM);

    // 3 launches total: gemm (zeroes agg/denom) -> edge -> finalize
    gemm_kernel<<<(N_NODES + BM - 1) / BM, 256, GEMM_SMEM>>>(x, w, att);
    edge_fused<<<(E_rand * 16 + 255) / 256, 256>>>(src, dst, E_rand);
    finalize_kernel<<<(N_NODES + 7) / 8, 256>>>(bias, out);
}